// round 1
// baseline (speedup 1.0000x reference)
#include <cuda_runtime.h>
#include <math.h>

#define Bsz 4096
#define Ssz 16
#define Gsz 128
#define Esz 256
#define Hsz 512
#define Psz 16
#define KCAT (Esz + Hsz)   /* 768 */
#define NG   (4 * Hsz)     /* 2048 */

// ---------------- scratch (device globals; no allocation allowed) ----------------
__device__ float g_emb[Bsz * Ssz * Esz];   // (B,S,E)
__device__ float g_ref[Bsz * Ssz * Hsz];   // encoder hidden states (B,S,H)
__device__ float g_u2 [Bsz * Ssz * Hsz];   // Wref2 @ ref + bref2
__device__ float g_h0 [Bsz * Hsz];
__device__ float g_h1 [Bsz * Hsz];
__device__ float g_c  [Bsz * Hsz];
__device__ float g_din[Bsz * Esz];
__device__ float g_qp [Bsz * Hsz];
__device__ float g_mask[Bsz * Ssz];
__device__ float g_ll [Bsz];
__device__ int   g_pi [Bsz * Psz];
__device__ float g_Wenc[NG * KCAT];        // gate-interleaved [Wih|Whh]
__device__ float g_benc[NG];
__device__ float g_Wdec[NG * KCAT];
__device__ float g_bdec[NG];

static __device__ __forceinline__ float sigf(float x) { return 1.0f / (1.0f + expf(-x)); }

// ---------------- weight reorder: new row 4*j+g <- old row g*H+j, cols = [Wih|Whh] ----
__global__ void reorder_k(const float* __restrict__ Wih, const float* __restrict__ Whh,
                          const float* __restrict__ b,
                          float* __restrict__ Wcat, float* __restrict__ bcat)
{
    int idx = blockIdx.x * blockDim.x + threadIdx.x;
    if (idx >= NG * KCAT) return;
    int r = idx / KCAT, k = idx % KCAT;
    int j = r >> 2, g = r & 3;
    int ro = g * Hsz + j;
    Wcat[idx] = (k < Esz) ? Wih[ro * Esz + k] : Whh[ro * Hsz + (k - Esz)];
    if (k == 0) bcat[r] = b[ro];
}

// ---------------- init state ----------------
__global__ void init_k(const float* __restrict__ dec0)
{
    int i = blockIdx.x * blockDim.x + threadIdx.x;
    if (i < Bsz * Hsz) { g_h0[i] = 0.f; g_c[i] = 0.f; }
    if (i < Bsz * Ssz) g_mask[i] = 0.f;
    if (i < Bsz)       g_ll[i] = 0.f;
    if (i < Bsz * Esz) g_din[i] = dec0[i & (Esz - 1)];
}

// ---------------- SGEMM: C[m,n] = sum_k A[m,k]*W[n,k] (+bias) ; MODE2 = fused LSTM ----
#define BM 128
#define BN 128
#define BK 8
#define BMP 136
#define BNP 136

template <int MODE>
__global__ __launch_bounds__(256, 2) void gemm_k(
    const float* __restrict__ A1, int lda1, int K1,
    const float* __restrict__ A2, int lda2,
    const float* __restrict__ W, int K,
    const float* __restrict__ bias,
    float* __restrict__ C, int N,
    float* __restrict__ cstate, float* __restrict__ hout,
    float* __restrict__ refout, int tstep)
{
    __shared__ __align__(16) float As[2][BK][BMP];
    __shared__ __align__(16) float Bs[2][BK][BNP];

    const int tid = threadIdx.x;
    const int tx = tid & 15, ty = tid >> 4;
    const int bm = blockIdx.y * BM, bn = blockIdx.x * BN;

    const int a_m = tid >> 1, a_k = (tid & 1) * 4;
    const int w_n = tid >> 1, w_k = (tid & 1) * 4;

    float acc[8][8];
#pragma unroll
    for (int i = 0; i < 8; i++)
#pragma unroll
        for (int j = 0; j < 8; j++) acc[i][j] = 0.f;

    const int nk = K / BK;
    const float* wp = W + (size_t)(bn + w_n) * K + w_k;

    auto loadA = [&](int k0) -> float4 {
        int kg = k0 + a_k;
        int m = bm + a_m;
        const float* p = (kg < K1) ? (A1 + (size_t)m * lda1 + kg)
                                   : (A2 + (size_t)m * lda2 + (kg - K1));
        return *reinterpret_cast<const float4*>(p);
    };

    float4 av = loadA(0);
    float4 wv = *reinterpret_cast<const float4*>(wp);

    int buf = 0;
    As[0][a_k + 0][a_m] = av.x; As[0][a_k + 1][a_m] = av.y;
    As[0][a_k + 2][a_m] = av.z; As[0][a_k + 3][a_m] = av.w;
    Bs[0][w_k + 0][w_n] = wv.x; Bs[0][w_k + 1][w_n] = wv.y;
    Bs[0][w_k + 2][w_n] = wv.z; Bs[0][w_k + 3][w_n] = wv.w;
    __syncthreads();

    for (int kt = 0; kt < nk; kt++) {
        float4 av2, wv2;
        if (kt + 1 < nk) {
            av2 = loadA((kt + 1) * BK);
            wv2 = *reinterpret_cast<const float4*>(wp + (kt + 1) * BK);
        }
#pragma unroll
        for (int kk = 0; kk < BK; kk++) {
            float a[8], bfr[8];
            *reinterpret_cast<float4*>(&a[0])   = *reinterpret_cast<const float4*>(&As[buf][kk][ty * 8]);
            *reinterpret_cast<float4*>(&a[4])   = *reinterpret_cast<const float4*>(&As[buf][kk][ty * 8 + 4]);
            *reinterpret_cast<float4*>(&bfr[0]) = *reinterpret_cast<const float4*>(&Bs[buf][kk][tx * 8]);
            *reinterpret_cast<float4*>(&bfr[4]) = *reinterpret_cast<const float4*>(&Bs[buf][kk][tx * 8 + 4]);
#pragma unroll
            for (int i = 0; i < 8; i++)
#pragma unroll
                for (int j = 0; j < 8; j++) acc[i][j] += a[i] * bfr[j];
        }
        if (kt + 1 < nk) {
            buf ^= 1;
            As[buf][a_k + 0][a_m] = av2.x; As[buf][a_k + 1][a_m] = av2.y;
            As[buf][a_k + 2][a_m] = av2.z; As[buf][a_k + 3][a_m] = av2.w;
            Bs[buf][w_k + 0][w_n] = wv2.x; Bs[buf][w_k + 1][w_n] = wv2.y;
            Bs[buf][w_k + 2][w_n] = wv2.z; Bs[buf][w_k + 3][w_n] = wv2.w;
            __syncthreads();
        }
    }

    const int n0 = bn + tx * 8;
    if (MODE == 0) {
        float bb[8];
#pragma unroll
        for (int j = 0; j < 8; j++) bb[j] = bias ? bias[n0 + j] : 0.f;
#pragma unroll
        for (int i = 0; i < 8; i++) {
            int m = bm + ty * 8 + i;
            float4 v0 = make_float4(acc[i][0] + bb[0], acc[i][1] + bb[1],
                                    acc[i][2] + bb[2], acc[i][3] + bb[3]);
            float4 v1 = make_float4(acc[i][4] + bb[4], acc[i][5] + bb[5],
                                    acc[i][6] + bb[6], acc[i][7] + bb[7]);
            float* cp = C + (size_t)m * N + n0;
            *reinterpret_cast<float4*>(cp)     = v0;
            *reinterpret_cast<float4*>(cp + 4) = v1;
        }
    } else {
        // LSTM epilogue: columns are gate-interleaved, 4 per unit (i,f,g,o)
        float bb[8];
#pragma unroll
        for (int j = 0; j < 8; j++) bb[j] = bias[n0 + j];
        const int unit0 = n0 >> 2;  // 2 units per thread
#pragma unroll
        for (int i = 0; i < 8; i++) {
            int m = bm + ty * 8 + i;
#pragma unroll
            for (int u = 0; u < 2; u++) {
                int unit = unit0 + u;
                float ig = sigf(acc[i][4 * u + 0] + bb[4 * u + 0]);
                float fg = sigf(acc[i][4 * u + 1] + bb[4 * u + 1]);
                float gg = tanhf(acc[i][4 * u + 2] + bb[4 * u + 2]);
                float og = sigf(acc[i][4 * u + 3] + bb[4 * u + 3]);
                size_t ci = (size_t)m * Hsz + unit;
                float cn = fg * cstate[ci] + ig * gg;
                float hn = og * tanhf(cn);
                cstate[ci] = cn;
                hout[ci]   = hn;
                if (refout) refout[((size_t)m * Ssz + tstep) * Hsz + unit] = hn;
            }
        }
    }
}

// ---------------- pointer step: logits -> log_softmax -> argmax -> din/mask/ll ----------
__global__ void pointer_k(const float* __restrict__ qp, const float* __restrict__ u2,
                          const float* __restrict__ Vec2, const float* __restrict__ emb,
                          float* __restrict__ din, float* __restrict__ mask,
                          float* __restrict__ ll, int* __restrict__ pi, int p)
{
    const int b = blockIdx.x;
    const int tid = threadIdx.x;
    const int lane = tid & 31, w = tid >> 5;
    __shared__ float qs[Hsz], vs[Hsz], ls[Ssz];
    __shared__ int s_amax;

    qs[tid]       = qp[(size_t)b * Hsz + tid];
    qs[tid + 256] = qp[(size_t)b * Hsz + 256 + tid];
    vs[tid]       = Vec2[tid];
    vs[tid + 256] = Vec2[tid + 256];
    __syncthreads();

#pragma unroll
    for (int q = 0; q < 2; q++) {
        int ss = 2 * w + q;
        const float* up = u2 + ((size_t)b * Ssz + ss) * Hsz;
        float acc = 0.f;
#pragma unroll
        for (int it = 0; it < Hsz / 32; it++) {
            int h = lane + 32 * it;
            acc += vs[h] * tanhf(qs[h] + up[h]);
        }
#pragma unroll
        for (int o = 16; o; o >>= 1) acc += __shfl_xor_sync(0xffffffffu, acc, o);
        if (lane == 0) ls[ss] = 10.0f * acc - 1e8f * mask[b * Ssz + ss];
    }
    __syncthreads();

    if (w == 0) {
        float v  = (lane < Ssz) ? ls[lane] : -INFINITY;
        int   id = (lane < Ssz) ? lane : Ssz;
        float bv = v; int bi = id;
#pragma unroll
        for (int o = 8; o; o >>= 1) {
            float ov = __shfl_xor_sync(0xffffffffu, bv, o);
            int   oi = __shfl_xor_sync(0xffffffffu, bi, o);
            if (ov > bv || (ov == bv && oi < bi)) { bv = ov; bi = oi; }
        }
        float ex = (lane < Ssz) ? expf(v - bv) : 0.f;
#pragma unroll
        for (int o = 16; o; o >>= 1) ex += __shfl_xor_sync(0xffffffffu, ex, o);
        if (lane == 0) {
            float lse = bv + logf(ex);
            ll[b] += bv - lse;            // chosen log_p == max - lse
            pi[b * Psz + p] = bi;
            mask[b * Ssz + bi] += 1.0f;
            s_amax = bi;
        }
    }
    __syncthreads();
    din[(size_t)b * Esz + tid] = emb[((size_t)b * Ssz + s_amax) * Esz + tid];
}

// ---------------- final mapping + output pack ----------------
__global__ void out_k(const int* __restrict__ pi, const float* __restrict__ ll,
                      void* __restrict__ out, int out_size)
{
    int b = blockIdx.x * blockDim.x + threadIdx.x;
    if (b >= Bsz) return;
    const int nodes[Psz] = {0,0,0,0, 1,1,1,1, 2,2,2,2, 3,3,3,3};
    int mp[Psz];
#pragma unroll
    for (int k = 0; k < Psz; k++) mp[k] = -1;
#pragma unroll
    for (int q = 0; q < Psz; q++) mp[pi[b * Psz + q]] = nodes[q];

    if (out_size >= Bsz * Psz + Bsz) {
        float* o = (float*)out;
#pragma unroll
        for (int k = 0; k < Psz; k++) o[b * Psz + k] = (float)mp[k];
        o[Bsz * Psz + b] = ll[b];
    } else {
        int* o = (int*)out;
#pragma unroll
        for (int k = 0; k < Psz; k++) o[b * Psz + k] = mp[k];
    }
}

// ---------------- host side ----------------
extern "C" void kernel_launch(void* const* d_in, const int* in_sizes, int n_in,
                              void* d_out, int out_size)
{
    const float* x        = (const float*)d_in[0];
    const float* emb_W    = (const float*)d_in[1];
    const float* enc_Wih  = (const float*)d_in[2];
    const float* enc_Whh  = (const float*)d_in[3];
    const float* enc_b    = (const float*)d_in[4];
    const float* dec_Wih  = (const float*)d_in[5];
    const float* dec_Whh  = (const float*)d_in[6];
    const float* dec_b    = (const float*)d_in[7];
    const float* Wq2      = (const float*)d_in[8];
    const float* bq2      = (const float*)d_in[9];
    const float* Wref2    = (const float*)d_in[10];
    const float* bref2    = (const float*)d_in[11];
    const float* Vec2     = (const float*)d_in[12];
    const float* dec0     = (const float*)d_in[13];

    float *emb, *ref, *u2, *h0, *h1, *c, *din, *qp, *mask, *ll;
    float *Wenc, *benc, *Wdec, *bdec;
    int* pi;
    cudaGetSymbolAddress((void**)&emb,  g_emb);
    cudaGetSymbolAddress((void**)&ref,  g_ref);
    cudaGetSymbolAddress((void**)&u2,   g_u2);
    cudaGetSymbolAddress((void**)&h0,   g_h0);
    cudaGetSymbolAddress((void**)&h1,   g_h1);
    cudaGetSymbolAddress((void**)&c,    g_c);
    cudaGetSymbolAddress((void**)&din,  g_din);
    cudaGetSymbolAddress((void**)&qp,   g_qp);
    cudaGetSymbolAddress((void**)&mask, g_mask);
    cudaGetSymbolAddress((void**)&ll,   g_ll);
    cudaGetSymbolAddress((void**)&pi,   g_pi);
    cudaGetSymbolAddress((void**)&Wenc, g_Wenc);
    cudaGetSymbolAddress((void**)&benc, g_benc);
    cudaGetSymbolAddress((void**)&Wdec, g_Wdec);
    cudaGetSymbolAddress((void**)&bdec, g_bdec);

    const int RT = NG * KCAT;
    reorder_k<<<(RT + 255) / 256, 256>>>(enc_Wih, enc_Whh, enc_b, Wenc, benc);
    reorder_k<<<(RT + 255) / 256, 256>>>(dec_Wih, dec_Whh, dec_b, Wdec, bdec);
    init_k<<<(Bsz * Hsz + 255) / 256, 256>>>(dec0);

    // emb = x @ emb_W^T   (M=B*S, N=E, K=G)
    gemm_k<0><<<dim3(Esz / BN, (Bsz * Ssz) / BM), 256>>>(
        x, Gsz, Gsz, nullptr, 0, emb_W, Gsz, nullptr,
        emb, Esz, nullptr, nullptr, nullptr, 0);

    // ---- encoder ----
    float* hc = h0;
    float* hn = h1;
    for (int t = 0; t < Ssz; t++) {
        gemm_k<2><<<dim3(NG / BN, Bsz / BM), 256>>>(
            emb + (size_t)t * Esz, Ssz * Esz, Esz, hc, Hsz,
            Wenc, KCAT, benc, nullptr, NG, c, hn, ref, t);
        float* tmp = hc; hc = hn; hn = tmp;
    }

    // u2 = ref @ Wref2^T + bref2   (M=B*S, N=H, K=H)
    gemm_k<0><<<dim3(Hsz / BN, (Bsz * Ssz) / BM), 256>>>(
        ref, Hsz, Hsz, nullptr, 0, Wref2, Hsz, bref2,
        u2, Hsz, nullptr, nullptr, nullptr, 0);

    // ---- decoder ----
    for (int p = 0; p < Psz; p++) {
        gemm_k<2><<<dim3(NG / BN, Bsz / BM), 256>>>(
            din, Esz, Esz, hc, Hsz,
            Wdec, KCAT, bdec, nullptr, NG, c, hn, nullptr, 0);
        float* tmp = hc; hc = hn; hn = tmp;

        // qp = h @ Wq2^T + bq2
        gemm_k<0><<<dim3(Hsz / BN, Bsz / BM), 256>>>(
            hc, Hsz, Hsz, nullptr, 0, Wq2, Hsz, bq2,
            qp, Hsz, nullptr, nullptr, nullptr, 0);

        pointer_k<<<Bsz, 256>>>(qp, u2, Vec2, emb, din, mask, ll, pi, p);
    }

    out_k<<<(Bsz + 255) / 256, 256>>>(pi, ll, d_out, out_size);
}

// round 2
// speedup vs baseline: 1.1488x; 1.1488x over previous
#include <cuda_runtime.h>
#include <math.h>

#define Bsz 4096
#define Ssz 16
#define Gsz 128
#define Esz 256
#define Hsz 512
#define Psz 16
#define KCAT (Esz + Hsz)   /* 768 */
#define NG   (4 * Hsz)     /* 2048 */

// ---------------- scratch (device globals; no allocation allowed) ----------------
__device__ float g_emb[Bsz * Ssz * Esz];    // (B,S,E)
__device__ float g_ref[Bsz * Ssz * Hsz];    // encoder hidden states (B,S,H)
__device__ float g_u2 [Bsz * Ssz * Hsz];    // Wref2 @ ref + bref2
__device__ float g_inpenc[Bsz * Ssz * NG];  // emb @ enc_Wih^T (gate-interleaved)
__device__ float g_inpdec[Bsz * Ssz * NG];  // emb @ dec_Wih^T (gate-interleaved)
__device__ float g_dec0g[NG];               // dec_input0 @ dec_Wih^T
__device__ float g_h0 [Bsz * Hsz];
__device__ float g_h1 [Bsz * Hsz];
__device__ float g_c  [Bsz * Hsz];
__device__ float g_qp [Bsz * Hsz];
__device__ float g_mask[Bsz * Ssz];
__device__ float g_ll [Bsz];
__device__ int   g_pi [Bsz * Psz];
__device__ int   g_sel[Bsz];
__device__ float g_Wenc[NG * KCAT];         // gate-interleaved [Wih|Whh]
__device__ float g_benc[NG];
__device__ float g_Wdec[NG * KCAT];
__device__ float g_bdec[NG];

static __device__ __forceinline__ float sigf(float x) { return 1.0f / (1.0f + expf(-x)); }

// ---- packed f32x2 helpers (FFMA2 path: 2 FMA/lane/issue on sm_103a) ----
static __device__ __forceinline__ void ffma2(unsigned long long& d,
                                             unsigned long long a,
                                             unsigned long long b)
{
    asm("fma.rn.f32x2 %0, %1, %2, %0;" : "+l"(d) : "l"(a), "l"(b));
}
static __device__ __forceinline__ unsigned long long dup2(float a)
{
    unsigned long long r;
    asm("mov.b64 %0, {%1, %1};" : "=l"(r) : "f"(a));
    return r;
}
static __device__ __forceinline__ float2 unp2(unsigned long long v)
{
    float2 r;
    asm("mov.b64 {%0, %1}, %2;" : "=f"(r.x), "=f"(r.y) : "l"(v));
    return r;
}

// ---------------- weight reorder: new row 4*j+g <- old row g*H+j, cols = [Wih|Whh] ----
__global__ void reorder_k(const float* __restrict__ Wih, const float* __restrict__ Whh,
                          const float* __restrict__ b,
                          float* __restrict__ Wcat, float* __restrict__ bcat)
{
    int idx = blockIdx.x * blockDim.x + threadIdx.x;
    if (idx >= NG * KCAT) return;
    int r = idx / KCAT, k = idx % KCAT;
    int j = r >> 2, g = r & 3;
    int ro = g * Hsz + j;
    Wcat[idx] = (k < Esz) ? Wih[ro * Esz + k] : Whh[ro * Hsz + (k - Esz)];
    if (k == 0) bcat[r] = b[ro];
}

// ---------------- dec_input0 gate projection (tiny) ----------------
__global__ void dec0_k(const float* __restrict__ dec0, const float* __restrict__ Wdec,
                       float* __restrict__ out)
{
    int n = blockIdx.x * blockDim.x + threadIdx.x;
    if (n >= NG) return;
    float s = 0.f;
    const float* wr = Wdec + (size_t)n * KCAT;
#pragma unroll 8
    for (int k = 0; k < Esz; k++) s += dec0[k] * wr[k];
    out[n] = s;
}

// ---------------- init state ----------------
__global__ void init_k()
{
    int i = blockIdx.x * blockDim.x + threadIdx.x;
    if (i < Bsz * Hsz) { g_h0[i] = 0.f; g_c[i] = 0.f; }
    if (i < Bsz * Ssz) g_mask[i] = 0.f;
    if (i < Bsz)       g_ll[i] = 0.f;
}

// ---------------- SGEMM: C[m,n] = sum_k A[m,k]*W[n,k] (+bias) ; MODE1 = fused LSTM ----
#define BM 128
#define BN 128
#define BK 8
#define BMP 136
#define BNP 136

template <int MODE>
__global__ __launch_bounds__(256, 2) void gemm_k(
    const float* __restrict__ A, int lda,
    const float* __restrict__ W, int ldw, int K,
    const float* __restrict__ bias,
    float* __restrict__ C, int N,
    const float* __restrict__ inp, long long mstride,
    const int* __restrict__ sel, int trow,
    float* __restrict__ cstate, float* __restrict__ hout,
    float* __restrict__ refout)
{
    __shared__ __align__(16) float As[2][BK][BMP];
    __shared__ __align__(16) float Bs[2][BK][BNP];

    const int tid = threadIdx.x;
    const int tx = tid & 15, ty = tid >> 4;
    const int bm = blockIdx.y * BM, bn = blockIdx.x * BN;

    const int l_m = tid >> 1, l_k = (tid & 1) * 4;

    const float* ap = A + (size_t)(bm + l_m) * lda + l_k;
    const float* wp = W + (size_t)(bn + l_m) * ldw + l_k;

    unsigned long long acc2[8][4];
#pragma unroll
    for (int i = 0; i < 8; i++)
#pragma unroll
        for (int j = 0; j < 4; j++) acc2[i][j] = 0ULL;

    const int nk = K / BK;

    float4 av = *reinterpret_cast<const float4*>(ap);
    float4 wv = *reinterpret_cast<const float4*>(wp);

    int buf = 0;
    As[0][l_k + 0][l_m] = av.x; As[0][l_k + 1][l_m] = av.y;
    As[0][l_k + 2][l_m] = av.z; As[0][l_k + 3][l_m] = av.w;
    Bs[0][l_k + 0][l_m] = wv.x; Bs[0][l_k + 1][l_m] = wv.y;
    Bs[0][l_k + 2][l_m] = wv.z; Bs[0][l_k + 3][l_m] = wv.w;
    __syncthreads();

    for (int kt = 0; kt < nk; kt++) {
        float4 av2, wv2;
        if (kt + 1 < nk) {
            av2 = *reinterpret_cast<const float4*>(ap + (kt + 1) * BK);
            wv2 = *reinterpret_cast<const float4*>(wp + (kt + 1) * BK);
        }
#pragma unroll
        for (int kk = 0; kk < BK; kk++) {
            float a[8];
            *reinterpret_cast<float4*>(&a[0]) = *reinterpret_cast<const float4*>(&As[buf][kk][ty * 8]);
            *reinterpret_cast<float4*>(&a[4]) = *reinterpret_cast<const float4*>(&As[buf][kk][ty * 8 + 4]);
            unsigned long long bp[4];
            *reinterpret_cast<ulonglong2*>(&bp[0]) = *reinterpret_cast<const ulonglong2*>(&Bs[buf][kk][tx * 8]);
            *reinterpret_cast<ulonglong2*>(&bp[2]) = *reinterpret_cast<const ulonglong2*>(&Bs[buf][kk][tx * 8 + 4]);
            unsigned long long aa[8];
#pragma unroll
            for (int i = 0; i < 8; i++) aa[i] = dup2(a[i]);
#pragma unroll
            for (int i = 0; i < 8; i++)
#pragma unroll
                for (int j = 0; j < 4; j++) ffma2(acc2[i][j], aa[i], bp[j]);
        }
        if (kt + 1 < nk) {
            buf ^= 1;
            As[buf][l_k + 0][l_m] = av2.x; As[buf][l_k + 1][l_m] = av2.y;
            As[buf][l_k + 2][l_m] = av2.z; As[buf][l_k + 3][l_m] = av2.w;
            Bs[buf][l_k + 0][l_m] = wv2.x; Bs[buf][l_k + 1][l_m] = wv2.y;
            Bs[buf][l_k + 2][l_m] = wv2.z; Bs[buf][l_k + 3][l_m] = wv2.w;
            __syncthreads();
        }
    }

    const int n0 = bn + tx * 8;
    if (MODE == 0) {
        float bb[8];
#pragma unroll
        for (int j = 0; j < 8; j++) bb[j] = bias ? bias[n0 + j] : 0.f;
#pragma unroll
        for (int i = 0; i < 8; i++) {
            int m = bm + ty * 8 + i;
            float o[8];
#pragma unroll
            for (int j = 0; j < 4; j++) {
                float2 v = unp2(acc2[i][j]);
                o[2 * j]     = v.x + bb[2 * j];
                o[2 * j + 1] = v.y + bb[2 * j + 1];
            }
            float* cp = C + (size_t)m * N + n0;
            *reinterpret_cast<float4*>(cp)     = make_float4(o[0], o[1], o[2], o[3]);
            *reinterpret_cast<float4*>(cp + 4) = make_float4(o[4], o[5], o[6], o[7]);
        }
    } else {
        // LSTM epilogue: columns are gate-interleaved, 4 per unit (i,f,g,o)
        float bb[8];
#pragma unroll
        for (int j = 0; j < 8; j++) bb[j] = bias[n0 + j];
        const int unit0 = n0 >> 2;  // 2 units per thread
#pragma unroll
        for (int i = 0; i < 8; i++) {
            int m = bm + ty * 8 + i;
            long long off = (long long)m * mstride + (long long)(sel ? sel[m] : trow) * NG;
            const float* ip = inp + off + n0;
            float4 g0 = *reinterpret_cast<const float4*>(ip);
            float4 g1 = *reinterpret_cast<const float4*>(ip + 4);
            float g[8] = {g0.x, g0.y, g0.z, g0.w, g1.x, g1.y, g1.z, g1.w};
#pragma unroll
            for (int j = 0; j < 4; j++) {
                float2 v = unp2(acc2[i][j]);
                g[2 * j]     += v.x + bb[2 * j];
                g[2 * j + 1] += v.y + bb[2 * j + 1];
            }
#pragma unroll
            for (int u = 0; u < 2; u++) {
                int unit = unit0 + u;
                float ig = sigf(g[4 * u + 0]);
                float fg = sigf(g[4 * u + 1]);
                float gg = tanhf(g[4 * u + 2]);
                float og = sigf(g[4 * u + 3]);
                size_t ci = (size_t)m * Hsz + unit;
                float cn = fg * cstate[ci] + ig * gg;
                float hn = og * tanhf(cn);
                cstate[ci] = cn;
                hout[ci]   = hn;
                if (refout) refout[((size_t)m * Ssz + trow) * Hsz + unit] = hn;
            }
        }
    }
}

// ---------------- pointer step: logits -> log_softmax -> argmax -> sel/mask/ll ----------
__global__ void pointer_k(const float* __restrict__ qp, const float* __restrict__ u2,
                          const float* __restrict__ Vec2,
                          float* __restrict__ mask, float* __restrict__ ll,
                          int* __restrict__ pi, int* __restrict__ sel, int p)
{
    const int b = blockIdx.x;
    const int tid = threadIdx.x;
    const int lane = tid & 31, w = tid >> 5;
    __shared__ float qs[Hsz], vs[Hsz], ls[Ssz];

    qs[tid]       = qp[(size_t)b * Hsz + tid];
    qs[tid + 256] = qp[(size_t)b * Hsz + 256 + tid];
    vs[tid]       = Vec2[tid];
    vs[tid + 256] = Vec2[tid + 256];
    __syncthreads();

#pragma unroll
    for (int q = 0; q < 2; q++) {
        int ss = 2 * w + q;
        const float* up = u2 + ((size_t)b * Ssz + ss) * Hsz;
        float acc = 0.f;
#pragma unroll
        for (int it = 0; it < Hsz / 32; it++) {
            int h = lane + 32 * it;
            acc += vs[h] * tanhf(qs[h] + up[h]);
        }
#pragma unroll
        for (int o = 16; o; o >>= 1) acc += __shfl_xor_sync(0xffffffffu, acc, o);
        if (lane == 0) ls[ss] = 10.0f * acc - 1e8f * mask[b * Ssz + ss];
    }
    __syncthreads();

    if (w == 0) {
        float v  = (lane < Ssz) ? ls[lane] : -INFINITY;
        int   id = (lane < Ssz) ? lane : Ssz;
        float bv = v; int bi = id;
#pragma unroll
        for (int o = 8; o; o >>= 1) {
            float ov = __shfl_xor_sync(0xffffffffu, bv, o);
            int   oi = __shfl_xor_sync(0xffffffffu, bi, o);
            if (ov > bv || (ov == bv && oi < bi)) { bv = ov; bi = oi; }
        }
        float ex = (lane < Ssz) ? expf(v - bv) : 0.f;
#pragma unroll
        for (int o = 16; o; o >>= 1) ex += __shfl_xor_sync(0xffffffffu, ex, o);
        if (lane == 0) {
            float lse = bv + logf(ex);
            ll[b] += bv - lse;            // chosen log_p == max - lse
            pi[b * Psz + p] = bi;
            sel[b] = bi;
            mask[b * Ssz + bi] += 1.0f;
        }
    }
}

// ---------------- final mapping + output pack ----------------
__global__ void out_k(const int* __restrict__ pi, const float* __restrict__ ll,
                      void* __restrict__ out, int out_size)
{
    int b = blockIdx.x * blockDim.x + threadIdx.x;
    if (b >= Bsz) return;
    const int nodes[Psz] = {0,0,0,0, 1,1,1,1, 2,2,2,2, 3,3,3,3};
    int mp[Psz];
#pragma unroll
    for (int k = 0; k < Psz; k++) mp[k] = -1;
#pragma unroll
    for (int q = 0; q < Psz; q++) mp[pi[b * Psz + q]] = nodes[q];

    if (out_size >= Bsz * Psz + Bsz) {
        float* o = (float*)out;
#pragma unroll
        for (int k = 0; k < Psz; k++) o[b * Psz + k] = (float)mp[k];
        o[Bsz * Psz + b] = ll[b];
    } else {
        int* o = (int*)out;
#pragma unroll
        for (int k = 0; k < Psz; k++) o[b * Psz + k] = mp[k];
    }
}

// ---------------- host side ----------------
extern "C" void kernel_launch(void* const* d_in, const int* in_sizes, int n_in,
                              void* d_out, int out_size)
{
    const float* x        = (const float*)d_in[0];
    const float* emb_W    = (const float*)d_in[1];
    const float* enc_Wih  = (const float*)d_in[2];
    const float* enc_Whh  = (const float*)d_in[3];
    const float* enc_b    = (const float*)d_in[4];
    const float* dec_Wih  = (const float*)d_in[5];
    const float* dec_Whh  = (const float*)d_in[6];
    const float* dec_b    = (const float*)d_in[7];
    const float* Wq2      = (const float*)d_in[8];
    const float* bq2      = (const float*)d_in[9];
    const float* Wref2    = (const float*)d_in[10];
    const float* bref2    = (const float*)d_in[11];
    const float* Vec2     = (const float*)d_in[12];
    const float* dec0     = (const float*)d_in[13];

    float *emb, *ref, *u2, *inpenc, *inpdec, *dec0g, *h0, *h1, *c, *qp, *mask, *ll;
    float *Wenc, *benc, *Wdec, *bdec;
    int *pi, *sel;
    cudaGetSymbolAddress((void**)&emb,    g_emb);
    cudaGetSymbolAddress((void**)&ref,    g_ref);
    cudaGetSymbolAddress((void**)&u2,     g_u2);
    cudaGetSymbolAddress((void**)&inpenc, g_inpenc);
    cudaGetSymbolAddress((void**)&inpdec, g_inpdec);
    cudaGetSymbolAddress((void**)&dec0g,  g_dec0g);
    cudaGetSymbolAddress((void**)&h0,     g_h0);
    cudaGetSymbolAddress((void**)&h1,     g_h1);
    cudaGetSymbolAddress((void**)&c,      g_c);
    cudaGetSymbolAddress((void**)&qp,     g_qp);
    cudaGetSymbolAddress((void**)&mask,   g_mask);
    cudaGetSymbolAddress((void**)&ll,     g_ll);
    cudaGetSymbolAddress((void**)&pi,     g_pi);
    cudaGetSymbolAddress((void**)&sel,    g_sel);
    cudaGetSymbolAddress((void**)&Wenc,   g_Wenc);
    cudaGetSymbolAddress((void**)&benc,   g_benc);
    cudaGetSymbolAddress((void**)&Wdec,   g_Wdec);
    cudaGetSymbolAddress((void**)&bdec,   g_bdec);

    const int RT = NG * KCAT;
    reorder_k<<<(RT + 255) / 256, 256>>>(enc_Wih, enc_Whh, enc_b, Wenc, benc);
    reorder_k<<<(RT + 255) / 256, 256>>>(dec_Wih, dec_Whh, dec_b, Wdec, bdec);
    init_k<<<(Bsz * Hsz + 255) / 256, 256>>>();
    dec0_k<<<NG / 256, 256>>>(dec0, Wdec, dec0g);

    // emb = x @ emb_W^T   (M=B*S, N=E, K=G)
    gemm_k<0><<<dim3(Esz / BN, (Bsz * Ssz) / BM), 256>>>(
        x, Gsz, emb_W, Gsz, Gsz, nullptr,
        emb, Esz, nullptr, 0, nullptr, 0, nullptr, nullptr, nullptr);

    // inp_enc = emb @ enc_Wih^T (gate-interleaved) : one big parallel GEMM
    gemm_k<0><<<dim3(NG / BN, (Bsz * Ssz) / BM), 256>>>(
        emb, Esz, Wenc, KCAT, Esz, nullptr,
        inpenc, NG, nullptr, 0, nullptr, 0, nullptr, nullptr, nullptr);

    // inp_dec = emb @ dec_Wih^T
    gemm_k<0><<<dim3(NG / BN, (Bsz * Ssz) / BM), 256>>>(
        emb, Esz, Wdec, KCAT, Esz, nullptr,
        inpdec, NG, nullptr, 0, nullptr, 0, nullptr, nullptr, nullptr);

    // ---- encoder: per-step GEMM only over h (K=512), input gates precomputed ----
    float* hc = h0;
    float* hn = h1;
    for (int t = 0; t < Ssz; t++) {
        gemm_k<1><<<dim3(NG / BN, Bsz / BM), 256>>>(
            hc, Hsz, Wenc + Esz, KCAT, Hsz, benc,
            nullptr, 0, inpenc, (long long)Ssz * NG, nullptr, t, c, hn, ref);
        float* tmp = hc; hc = hn; hn = tmp;
    }

    // u2 = ref @ Wref2^T + bref2   (M=B*S, N=H, K=H)
    gemm_k<0><<<dim3(Hsz / BN, (Bsz * Ssz) / BM), 256>>>(
        ref, Hsz, Wref2, Hsz, Hsz, bref2,
        u2, Hsz, nullptr, 0, nullptr, 0, nullptr, nullptr, nullptr);

    // ---- decoder ----
    for (int p = 0; p < Psz; p++) {
        if (p == 0) {
            gemm_k<1><<<dim3(NG / BN, Bsz / BM), 256>>>(
                hc, Hsz, Wdec + Esz, KCAT, Hsz, bdec,
                nullptr, 0, dec0g, 0LL, nullptr, 0, c, hn, nullptr);
        } else {
            gemm_k<1><<<dim3(NG / BN, Bsz / BM), 256>>>(
                hc, Hsz, Wdec + Esz, KCAT, Hsz, bdec,
                nullptr, 0, inpdec, (long long)Ssz * NG, sel, 0, c, hn, nullptr);
        }
        float* tmp = hc; hc = hn; hn = tmp;

        // qp = h @ Wq2^T + bq2
        gemm_k<0><<<dim3(Hsz / BN, Bsz / BM), 256>>>(
            hc, Hsz, Wq2, Hsz, Hsz, bq2,
            qp, Hsz, nullptr, 0, nullptr, 0, nullptr, nullptr, nullptr);

        pointer_k<<<Bsz, 256>>>(qp, u2, Vec2, mask, ll, pi, sel, p);
    }

    out_k<<<(Bsz + 255) / 256, 256>>>(pi, ll, d_out, out_size);
}